// round 13
// baseline (speedup 1.0000x reference)
#include <cuda_runtime.h>
#include <cuda_fp16.h>
#include <cstdint>

#define NATOMS 25000
#define MNBR 32
#define DIM 128
#define MGRID64 391          // ceil(25000/64)
#define NGATHER 3125         // ceil(25000/8)
#define TILE64 17408         // 64 rows * 272B stride
#define WTILE 34816          // 128 rows * 272B stride

// ---------------- scratch (device globals) ----------------
__device__ float g_A[(size_t)NATOMS * DIM];           // X@W1top + b1 (f32, gather self term)
__device__ __half g_B[(size_t)NATOMS * DIM];          // X@W1bot (fp16, gather bulk reads)
__device__ __half g_H[(size_t)NATOMS * DIM];          // gather output (fp16)
// fp16 weights in ORIGINAL [k][n] layout (plain elementwise casts)
__device__ __half g_w2[128 * 128];   // msgW2
__device__ __half g_u1[256 * 128];   // updW1 (K=256 rows, N=128)
__device__ __half g_u2[128 * 128];   // updW2

// ---------------- helpers ----------------
__device__ __forceinline__ uint32_t smem_u32(const void* p) {
    uint32_t a;
    asm("{ .reg .u64 t; cvta.to.shared.u64 t, %1; cvt.u32.u64 %0, t; }" : "=r"(a) : "l"(p));
    return a;
}
__device__ __forceinline__ void ldmat_x4(uint32_t* r, uint32_t a) {
    asm volatile("ldmatrix.sync.aligned.m8n8.x4.shared.b16 {%0,%1,%2,%3}, [%4];"
        : "=r"(r[0]), "=r"(r[1]), "=r"(r[2]), "=r"(r[3]) : "r"(a));
}
__device__ __forceinline__ void ldmat_x4_trans(uint32_t* r, uint32_t a) {
    asm volatile("ldmatrix.sync.aligned.m8n8.x4.trans.shared.b16 {%0,%1,%2,%3}, [%4];"
        : "=r"(r[0]), "=r"(r[1]), "=r"(r[2]), "=r"(r[3]) : "r"(a));
}
__device__ __forceinline__ void hmma(float* d, const uint32_t* a, uint2 b) {
    asm volatile("mma.sync.aligned.m16n8k16.row.col.f32.f16.f16.f32 "
        "{%0,%1,%2,%3}, {%4,%5,%6,%7}, {%8,%9}, {%0,%1,%2,%3};"
        : "+f"(d[0]), "+f"(d[1]), "+f"(d[2]), "+f"(d[3])
        : "r"(a[0]), "r"(a[1]), "r"(a[2]), "r"(a[3]), "r"(b.x), "r"(b.y));
}
__device__ __forceinline__ void cp16(uint32_t dst, const void* src) {
    asm volatile("cp.async.cg.shared.global [%0], [%1], 16;" :: "r"(dst), "l"(src) : "memory");
}
#define CP_COMMIT() asm volatile("cp.async.commit_group;" ::: "memory")
#define CP_WAIT(n)  asm volatile("cp.async.wait_group %0;" :: "n"(n) : "memory")

// ---------------- async tile copies ([k][n] rows, 272B stride), 256 threads ----------------
// 128 k-rows x 128 n fp16
__device__ __forceinline__ void cp_w_tile(uint32_t smoff, const __half* __restrict__ src) {
    int tid = threadIdx.x;
#pragma unroll
    for (int q = 0; q < 8; ++q) {
        int s = tid + q * 256;
        int r = s >> 4, c8 = (s & 15) << 3;
        cp16(smoff + r * 272 + (c8 << 1), src + (size_t)r * 128 + c8);
    }
}
// 64-row fp16 A tile via cp.async
__device__ __forceinline__ void cp_a_tile(uint32_t smoff, const __half* __restrict__ src,
                                          int m0, int M) {
    int tid = threadIdx.x;
#pragma unroll
    for (int q = 0; q < 4; ++q) {
        int s = tid + q * 256;
        int r = s >> 4, c8 = (s & 15) << 3;
        int gr = m0 + r; if (gr >= M) gr = M - 1;
        cp16(smoff + r * 272 + (c8 << 1), src + (size_t)gr * DIM + c8);
    }
}
// f32 [128k][128n] weight tile -> fp16 smem [k][n] (head w1 conversion, coalesced)
__device__ __forceinline__ void conv_w1_tile(char* sm, int off, const float* __restrict__ src) {
    int tid = threadIdx.x;
#pragma unroll
    for (int q = 0; q < 16; ++q) {
        int s = tid + q * 256;
        int r = s >> 5, c4 = (s & 31) << 2;
        float4 f = *reinterpret_cast<const float4*>(src + (size_t)r * 128 + c4);
        __half2 h01 = __floats2half2_rn(f.x, f.y);
        __half2 h23 = __floats2half2_rn(f.z, f.w);
        *reinterpret_cast<uint2*>(sm + off + r * 272 + (c4 << 1)) =
            make_uint2(*reinterpret_cast<uint32_t*>(&h01), *reinterpret_cast<uint32_t*>(&h23));
    }
}
// f32 -> fp16 hi/lo split into two 64-row tiles (head kernel, 256 thr)
__device__ __forceinline__ void load_x_split64(char* sm, int offh, int offl,
                                               const float* __restrict__ X, int m0, int M) {
    int tid = threadIdx.x;
#pragma unroll
    for (int q = 0; q < 8; ++q) {
        int s = tid + q * 256;
        int r = s >> 5, c4 = (s & 31) << 2;
        int gr = m0 + r; if (gr >= M) gr = M - 1;
        float4 f = *reinterpret_cast<const float4*>(X + (size_t)gr * DIM + c4);
        float v[4] = {f.x, f.y, f.z, f.w};
        uint32_t ph[2], pl[2];
#pragma unroll
        for (int e = 0; e < 2; ++e) {
            __half h0 = __float2half_rn(v[2 * e]), h1 = __float2half_rn(v[2 * e + 1]);
            __half l0 = __float2half_rn(v[2 * e] - __half2float(h0));
            __half l1 = __float2half_rn(v[2 * e + 1] - __half2float(h1));
            ph[e] = ((uint32_t)__half_as_ushort(h1) << 16) | __half_as_ushort(h0);
            pl[e] = ((uint32_t)__half_as_ushort(l1) << 16) | __half_as_ushort(l0);
        }
        *reinterpret_cast<uint2*>(sm + offh + r * 272 + (c4 << 1)) = make_uint2(ph[0], ph[1]);
        *reinterpret_cast<uint2*>(sm + offl + r * 272 + (c4 << 1)) = make_uint2(pl[0], pl[1]);
    }
}
// f32 -> single fp16 into one 64-row tile (tail kernel, 256 thr)
__device__ __forceinline__ void load_x_half64(char* sm, int off,
                                              const float* __restrict__ X, int m0, int M) {
    int tid = threadIdx.x;
#pragma unroll
    for (int q = 0; q < 8; ++q) {
        int s = tid + q * 256;
        int r = s >> 5, c4 = (s & 31) << 2;
        int gr = m0 + r; if (gr >= M) gr = M - 1;
        float4 f = *reinterpret_cast<const float4*>(X + (size_t)gr * DIM + c4);
        __half2 h01 = __floats2half2_rn(f.x, f.y);
        __half2 h23 = __floats2half2_rn(f.z, f.w);
        *reinterpret_cast<uint2*>(sm + off + r * 272 + (c4 << 1)) =
            make_uint2(*reinterpret_cast<uint32_t*>(&h01), *reinterpret_cast<uint32_t*>(&h23));
    }
}

// ---------------- B-fragment loader: ldmatrix.trans on [k][n] smem ----------------
// mats: [jj k-lo, jj k-hi, jj+1 k-lo, jj+1 k-hi]
__device__ __forceinline__ void ldB(uint32_t* w4, uint32_t base, int k0, int n0w, int jj, int lane) {
    int kk = k0 + ((lane >> 3) & 1) * 8 + (lane & 7);
    int nn = n0w + (jj + (lane >> 4)) * 8;
    ldmat_x4_trans(w4, base + (uint32_t)(kk * 272 + nn * 2));
}

// ---------------- 2-product core (head, 32x32 warp tile): d += Ah@W + Al@W ----------------
__device__ __forceinline__ void gemm_tiles2(uint32_t smb, int offAh, int offAl, int offW,
                                            int m0w, int n0w, int lane,
                                            float (&d)[2][4][4]) {
#pragma unroll
    for (int k0 = 0; k0 < 128; k0 += 16) {
        uint32_t ah[2][4], al[2][4];
#pragma unroll
        for (int i = 0; i < 2; ++i) {
            uint32_t ra = (uint32_t)((m0w + i * 16 + (lane & 15)) * 272 +
                                     ((k0 + ((lane >> 4) << 3)) << 1));
            ldmat_x4(ah[i], smb + offAh + ra);
            ldmat_x4(al[i], smb + offAl + ra);
        }
        uint2 wb[4];
#pragma unroll
        for (int jj = 0; jj < 4; jj += 2) {
            uint32_t w4[4];
            ldB(w4, smb + offW, k0, n0w, jj, lane);
            wb[jj]     = make_uint2(w4[0], w4[1]);
            wb[jj + 1] = make_uint2(w4[2], w4[3]);
        }
#pragma unroll
        for (int j = 0; j < 4; ++j) {
            hmma(d[0][j], ah[0], wb[j]);
            hmma(d[1][j], ah[1], wb[j]);
        }
#pragma unroll
        for (int j = 0; j < 4; ++j) {
            hmma(d[0][j], al[0], wb[j]);
            hmma(d[1][j], al[1], wb[j]);
        }
    }
}
// ---------------- 1-product core (tail, 32x32 warp tile): d += A@W ----------------
__device__ __forceinline__ void gemm_tiles1(uint32_t smb, int offA, int offW,
                                            int m0w, int n0w, int lane,
                                            float (&d)[2][4][4]) {
#pragma unroll
    for (int k0 = 0; k0 < 128; k0 += 16) {
        uint32_t a[2][4];
#pragma unroll
        for (int i = 0; i < 2; ++i) {
            uint32_t ra = (uint32_t)((m0w + i * 16 + (lane & 15)) * 272 +
                                     ((k0 + ((lane >> 4) << 3)) << 1));
            ldmat_x4(a[i], smb + offA + ra);
        }
        uint2 wb[4];
#pragma unroll
        for (int jj = 0; jj < 4; jj += 2) {
            uint32_t w4[4];
            ldB(w4, smb + offW, k0, n0w, jj, lane);
            wb[jj]     = make_uint2(w4[0], w4[1]);
            wb[jj + 1] = make_uint2(w4[2], w4[3]);
        }
#pragma unroll
        for (int j = 0; j < 4; ++j) {
            hmma(d[0][j], a[0], wb[j]);
            hmma(d[1][j], a[1], wb[j]);
        }
    }
}
__device__ __forceinline__ void zero_d(float (&d)[2][4][4]) {
#pragma unroll
    for (int i = 0; i < 2; ++i)
#pragma unroll
        for (int j = 0; j < 4; ++j)
#pragma unroll
            for (int e = 0; e < 4; ++e) d[i][j][e] = 0.f;
}
// write 32x32 register tile into smem as single fp16 (bias + optional relu)
template<bool RELU>
__device__ __forceinline__ void store_smem_half(char* sm, int off,
        float (&d)[2][4][4], const float* __restrict__ bias, float bscale,
        int m0w, int n0w, int lane) {
    int g = lane >> 2, tg = lane & 3;
#pragma unroll
    for (int j = 0; j < 4; ++j) {
        int c = n0w + j * 8 + 2 * tg;
        float b0 = bscale * __ldg(bias + c), b1 = bscale * __ldg(bias + c + 1);
#pragma unroll
        for (int i = 0; i < 2; ++i)
#pragma unroll
            for (int h = 0; h < 2; ++h) {
                int r = m0w + i * 16 + g + h * 8;
                float v0 = d[i][j][2 * h] + b0, v1 = d[i][j][2 * h + 1] + b1;
                if (RELU) { v0 = fmaxf(v0, 0.f); v1 = fmaxf(v1, 0.f); }
                __half2 hv = __floats2half2_rn(v0, v1);
                *reinterpret_cast<uint32_t*>(sm + off + r * 272 + c * 2) =
                    *reinterpret_cast<uint32_t*>(&hv);
            }
    }
}

// ---------------- head kernel: [A|B] = X @ [W1top|W1bot]; A += b1 (f32), B -> fp16 ----------------
// w1 converted inline from f32 (no conv_w dependency). smem = 2*TILE64 + 2*WTILE = 104448
__global__ __launch_bounds__(256, 2)
void head_kernel(const float* __restrict__ X,
                 const float* __restrict__ msgW1, const float* __restrict__ msgb1,
                 float* __restrict__ outA, __half* __restrict__ outB, int M)
{
    constexpr int S0 = 0, S1 = TILE64, W0 = 2 * TILE64, W1 = 2 * TILE64 + WTILE;
    extern __shared__ char smem[];
    const uint32_t smb = smem_u32(smem);
    const int tid = threadIdx.x, wid = tid >> 5, lane = tid & 31;
    const int g = lane >> 2, tg = lane & 3;
    const int m0 = blockIdx.x * 64;
    const int m0w = (wid & 1) * 32, n0w = (wid >> 1) * 32;

    conv_w1_tile(smem, W0, msgW1);                // W1top: rows 0-127
    conv_w1_tile(smem, W1, msgW1 + 128 * 128);    // W1bot: rows 128-255
    load_x_split64(smem, S0, S1, X, m0, M);
    __syncthreads();

#pragma unroll
    for (int p = 0; p < 2; ++p) {
        float d[2][4][4];
        zero_d(d);
        gemm_tiles2(smb, S0, S1, p ? W1 : W0, m0w, n0w, lane, d);
#pragma unroll
        for (int j = 0; j < 4; ++j) {
            int c = n0w + j * 8 + 2 * tg;
            float b0 = 0.f, b1 = 0.f;
            if (p == 0) { b0 = __ldg(msgb1 + c); b1 = __ldg(msgb1 + c + 1); }
#pragma unroll
            for (int i = 0; i < 2; ++i)
#pragma unroll
                for (int h = 0; h < 2; ++h) {
                    int m = m0 + m0w + i * 16 + g + h * 8;
                    if (m >= M) continue;
                    float v0 = d[i][j][2 * h] + b0, v1 = d[i][j][2 * h + 1] + b1;
                    if (p == 0) {
                        *reinterpret_cast<float2*>(outA + (size_t)m * DIM + c) =
                            make_float2(v0, v1);
                    } else {
                        *reinterpret_cast<__half2*>(outB + (size_t)m * DIM + c) =
                            __floats2half2_rn(v0, v1);
                    }
                }
        }
    }
}

// ---------------- fused tail: agg -> u -> out, X preloaded, cp.async double-buffered W ----------------
// smem = 2*TILE64 + 2*WTILE = 104448 -> 2 CTAs/SM
__global__ __launch_bounds__(256, 2)
void fused_tail_kernel(const __half* __restrict__ H,
                       const float* __restrict__ X,
                       const __half* __restrict__ w2, const __half* __restrict__ u1,
                       const __half* __restrict__ u2,
                       const float* __restrict__ msgb2, const float* __restrict__ updb1,
                       const float* __restrict__ updb2,
                       float* __restrict__ out, int M)
{
    constexpr int S0 = 0, S1 = TILE64, W0 = 2 * TILE64, W1 = 2 * TILE64 + WTILE;
    extern __shared__ char smem[];
    const uint32_t smb = smem_u32(smem);
    const int tid = threadIdx.x, wid = tid >> 5, lane = tid & 31;
    const int g = lane >> 2, tg = lane & 3;
    const int m0 = blockIdx.x * 64;
    const int m0w = (wid & 1) * 32, n0w = (wid >> 1) * 32;

    // prologue: g0 = {H, w2}, g1 = {u1 agg-part}; X -> S1 overlapped
    cp_a_tile(smb + S0, H, m0, M);
    cp_w_tile(smb + W0, w2);
    CP_COMMIT();                          // g0
    cp_w_tile(smb + W1, u1 + 128 * 128);  // u1 rows 128-255 (agg part)
    CP_COMMIT();                          // g1
    load_x_half64(smem, S1, X, m0, M);    // X -> S1 (regular loads, overlaps cp.async)
    CP_WAIT(1);                           // g0 done
    __syncthreads();

    // ---- stage 1: agg = H @ w2 + 32*b2 ----
    float d[2][4][4];
    zero_d(d);
    gemm_tiles1(smb, S0, W0, m0w, n0w, lane, d);
    __syncthreads();                      // H/w2 reads done
    store_smem_half<false>(smem, S0, d, msgb2, (float)MNBR, m0w, n0w, lane);  // agg -> S0
    cp_w_tile(smb + W0, u1);              // u1 rows 0-127 (X part) into freed W0
    CP_COMMIT();                          // g2
    CP_WAIT(1);                           // g1 done
    __syncthreads();                      // agg + u1-agg visible

    // ---- stage 2a: d = agg @ u1[128:] ----
    zero_d(d);
    gemm_tiles1(smb, S0, W1, m0w, n0w, lane, d);
    __syncthreads();                      // W1/S0 reads done
    cp_w_tile(smb + W1, u2);              // u2 into freed W1
    CP_COMMIT();                          // g3
    CP_WAIT(1);                           // g2 done
    __syncthreads();
    // ---- stage 2b: d += X @ u1[:128] ----
    gemm_tiles1(smb, S1, W0, m0w, n0w, lane, d);
    store_smem_half<true>(smem, S0, d, updb1, 1.f, m0w, n0w, lane);  // u -> S0 (2a S0 reads synced)
    CP_WAIT(0);                           // g3 done
    __syncthreads();                      // u stores + u2 visible

    // ---- stage 3: out = relu(X + u @ u2 + b2) ----
    zero_d(d);
    gemm_tiles1(smb, S0, W1, m0w, n0w, lane, d);
#pragma unroll
    for (int j = 0; j < 4; ++j) {
        int c = n0w + j * 8 + 2 * tg;
        float b0 = __ldg(updb2 + c), b1 = __ldg(updb2 + c + 1);
#pragma unroll
        for (int i = 0; i < 2; ++i)
#pragma unroll
            for (int h = 0; h < 2; ++h) {
                int m = m0 + m0w + i * 16 + g + h * 8;
                if (m >= M) continue;
                float2 rx = *reinterpret_cast<const float2*>(X + (size_t)m * DIM + c);
                float v0 = fmaxf(d[i][j][2 * h] + b0 + rx.x, 0.f);
                float v1 = fmaxf(d[i][j][2 * h + 1] + b1 + rx.y, 0.f);
                *reinterpret_cast<float2*>(out + (size_t)m * DIM + c) = make_float2(v0, v1);
            }
    }
}

// ---------------- gather + edge ReLU + sum; extra blocks convert tail weights ----------------
__global__ __launch_bounds__(256)
void gather_sum_kernel(const float* __restrict__ A,
                       const __half* __restrict__ B,
                       const void* __restrict__ idx_raw,
                       __half* __restrict__ H,
                       const float* __restrict__ msgW2, const float* __restrict__ updW1,
                       const float* __restrict__ updW2,
                       __half* __restrict__ w2, __half* __restrict__ u1,
                       __half* __restrict__ u2, int M)
{
    if (blockIdx.x >= NGATHER) {
        // weight conversion blocks: 64 blocks x 1024 elems, elementwise f32->fp16
        int e = (blockIdx.x - NGATHER) * 1024 + threadIdx.x * 4;
        const float* src; __half* dst; int off;
        if (e < 16384)      { src = msgW2; dst = w2; off = e; }
        else if (e < 49152) { src = updW1; dst = u1; off = e - 16384; }
        else                { src = updW2; dst = u2; off = e - 49152; }
        float4 f = *reinterpret_cast<const float4*>(src + off);
        __half2 h01 = __floats2half2_rn(f.x, f.y);
        __half2 h23 = __floats2half2_rn(f.z, f.w);
        *reinterpret_cast<uint2*>(dst + off) =
            make_uint2(*reinterpret_cast<uint32_t*>(&h01), *reinterpret_cast<uint32_t*>(&h23));
        return;
    }

    int node = blockIdx.x * 8 + (threadIdx.x >> 5);
    int lane = threadIdx.x & 31;
    if (node >= M) return;

    // int32 vs int64 index detection (int64 little-endian -> odd words all zero)
    const int* idx32 = (const int*)idx_raw;
    int w = idx32[(size_t)node * 32 + lane];
    unsigned zmask = __ballot_sync(0xffffffffu, w == 0);
    int j;
    if ((zmask & 0xAAAAAAAAu) == 0xAAAAAAAAu)
        j = (int)((const long long*)idx_raw)[(size_t)node * 32 + lane];
    else
        j = w;

    float4 a = reinterpret_cast<const float4*>(A + (size_t)node * DIM)[lane];
    float4 acc = make_float4(0.f, 0.f, 0.f, 0.f);
#pragma unroll
    for (int m = 0; m < 32; ++m) {
        int jm = __shfl_sync(0xffffffffu, j, m);
        uint2 raw = __ldg(reinterpret_cast<const uint2*>(B + (size_t)jm * DIM) + lane);
        float2 f01 = __half22float2(*reinterpret_cast<__half2*>(&raw.x));
        float2 f23 = __half22float2(*reinterpret_cast<__half2*>(&raw.y));
        acc.x += fmaxf(a.x + f01.x, 0.f);
        acc.y += fmaxf(a.y + f01.y, 0.f);
        acc.z += fmaxf(a.z + f23.x, 0.f);
        acc.w += fmaxf(a.w + f23.y, 0.f);
    }
    __half2 h01 = __floats2half2_rn(acc.x, acc.y);
    __half2 h23 = __floats2half2_rn(acc.z, acc.w);
    reinterpret_cast<uint2*>(H + (size_t)node * DIM)[lane] =
        make_uint2(*reinterpret_cast<uint32_t*>(&h01), *reinterpret_cast<uint32_t*>(&h23));
}

// ---------------- launch ----------------
extern "C" void kernel_launch(void* const* d_in, const int* in_sizes, int n_in,
                              void* d_out, int out_size)
{
    const float* X     = (const float*)d_in[0];
    const void*  idx   = d_in[2];
    const float* msgW1 = (const float*)d_in[3];
    const float* msgb1 = (const float*)d_in[4];
    const float* msgW2 = (const float*)d_in[5];
    const float* msgb2 = (const float*)d_in[6];
    const float* updW1 = (const float*)d_in[7];
    const float* updb1 = (const float*)d_in[8];
    const float* updW2 = (const float*)d_in[9];
    const float* updb2 = (const float*)d_in[10];
    float* out = (float*)d_out;

    float* A; __half* B;
    __half *H, *w2, *u1, *u2;
    cudaGetSymbolAddress((void**)&A, g_A);   cudaGetSymbolAddress((void**)&B, g_B);
    cudaGetSymbolAddress((void**)&H, g_H);
    cudaGetSymbolAddress((void**)&w2, g_w2);
    cudaGetSymbolAddress((void**)&u1, g_u1); cudaGetSymbolAddress((void**)&u2, g_u2);

    const int M = NATOMS;
    const int SMEM = 2 * TILE64 + 2 * WTILE;   // 104448 -> 2 CTAs/SM
    cudaFuncSetAttribute(head_kernel, cudaFuncAttributeMaxDynamicSharedMemorySize, SMEM);
    cudaFuncSetAttribute(fused_tail_kernel, cudaFuncAttributeMaxDynamicSharedMemorySize, SMEM);

    head_kernel<<<MGRID64, 256, SMEM>>>(X, msgW1, msgb1, A, B, M);
    gather_sum_kernel<<<NGATHER + 64, 256>>>(A, B, idx, H,
                                             msgW2, updW1, updW2, w2, u1, u2, M);
    fused_tail_kernel<<<MGRID64, 256, SMEM>>>(H, X, w2, u1, u2,
                                              msgb2, updb1, updb2, out, M);

    (void)in_sizes; (void)n_in; (void)out_size;
}

// round 14
// speedup vs baseline: 1.0039x; 1.0039x over previous
#include <cuda_runtime.h>
#include <cuda_fp16.h>
#include <cstdint>

#define NATOMS 25000
#define MNBR 32
#define DIM 128
#define MGRID64 391          // ceil(25000/64)
#define NGATHER 3125         // ceil(25000/8)
#define TILE64 17408         // 64 rows * 272B stride
#define WTILE 34816          // 128 rows * 272B stride

// ---------------- scratch (device globals) ----------------
__device__ float g_A[(size_t)NATOMS * DIM];           // X@W1top + b1 (f32, gather self term)
__device__ __half g_B[(size_t)NATOMS * DIM];          // X@W1bot (fp16, gather bulk reads)
__device__ __half g_H[(size_t)NATOMS * DIM];          // gather output (fp16)
// fp16 weights in ORIGINAL [k][n] layout (plain elementwise casts)
__device__ __half g_w1[256 * 128];   // msgW1 (K=256 rows: top|bot)
__device__ __half g_w2[128 * 128];   // msgW2
__device__ __half g_u1[256 * 128];   // updW1 (K=256 rows, N=128)
__device__ __half g_u2[128 * 128];   // updW2

// ---------------- helpers ----------------
__device__ __forceinline__ uint32_t smem_u32(const void* p) {
    uint32_t a;
    asm("{ .reg .u64 t; cvta.to.shared.u64 t, %1; cvt.u32.u64 %0, t; }" : "=r"(a) : "l"(p));
    return a;
}
__device__ __forceinline__ void ldmat_x4(uint32_t* r, uint32_t a) {
    asm volatile("ldmatrix.sync.aligned.m8n8.x4.shared.b16 {%0,%1,%2,%3}, [%4];"
        : "=r"(r[0]), "=r"(r[1]), "=r"(r[2]), "=r"(r[3]) : "r"(a));
}
__device__ __forceinline__ void ldmat_x4_trans(uint32_t* r, uint32_t a) {
    asm volatile("ldmatrix.sync.aligned.m8n8.x4.trans.shared.b16 {%0,%1,%2,%3}, [%4];"
        : "=r"(r[0]), "=r"(r[1]), "=r"(r[2]), "=r"(r[3]) : "r"(a));
}
__device__ __forceinline__ void hmma(float* d, const uint32_t* a, uint2 b) {
    asm volatile("mma.sync.aligned.m16n8k16.row.col.f32.f16.f16.f32 "
        "{%0,%1,%2,%3}, {%4,%5,%6,%7}, {%8,%9}, {%0,%1,%2,%3};"
        : "+f"(d[0]), "+f"(d[1]), "+f"(d[2]), "+f"(d[3])
        : "r"(a[0]), "r"(a[1]), "r"(a[2]), "r"(a[3]), "r"(b.x), "r"(b.y));
}
__device__ __forceinline__ void cp16(uint32_t dst, const void* src) {
    asm volatile("cp.async.cg.shared.global [%0], [%1], 16;" :: "r"(dst), "l"(src) : "memory");
}
#define CP_COMMIT() asm volatile("cp.async.commit_group;" ::: "memory")
#define CP_WAIT(n)  asm volatile("cp.async.wait_group %0;" :: "n"(n) : "memory")

// ---------------- w1 elementwise f32->fp16 (minimal prologue kernel) ----------------
__global__ void conv_w1_kernel(const float* __restrict__ msgW1, __half* __restrict__ w1) {
    int e = (blockIdx.x * 256 + threadIdx.x) * 4;
    float4 f = *reinterpret_cast<const float4*>(msgW1 + e);
    __half2 h01 = __floats2half2_rn(f.x, f.y);
    __half2 h23 = __floats2half2_rn(f.z, f.w);
    *reinterpret_cast<uint2*>(w1 + e) =
        make_uint2(*reinterpret_cast<uint32_t*>(&h01), *reinterpret_cast<uint32_t*>(&h23));
}

// ---------------- async tile copies ([k][n] rows, 272B stride), 256 threads ----------------
// 128 k-rows x 128 n fp16
__device__ __forceinline__ void cp_w_tile(uint32_t smoff, const __half* __restrict__ src) {
    int tid = threadIdx.x;
#pragma unroll
    for (int q = 0; q < 8; ++q) {
        int s = tid + q * 256;
        int r = s >> 4, c8 = (s & 15) << 3;
        cp16(smoff + r * 272 + (c8 << 1), src + (size_t)r * 128 + c8);
    }
}
// 64-row fp16 A tile via cp.async
__device__ __forceinline__ void cp_a_tile(uint32_t smoff, const __half* __restrict__ src,
                                          int m0, int M) {
    int tid = threadIdx.x;
#pragma unroll
    for (int q = 0; q < 4; ++q) {
        int s = tid + q * 256;
        int r = s >> 4, c8 = (s & 15) << 3;
        int gr = m0 + r; if (gr >= M) gr = M - 1;
        cp16(smoff + r * 272 + (c8 << 1), src + (size_t)gr * DIM + c8);
    }
}
// f32 -> fp16 hi/lo split into two 64-row tiles (head kernel, 256 thr)
__device__ __forceinline__ void load_x_split64(char* sm, int offh, int offl,
                                               const float* __restrict__ X, int m0, int M) {
    int tid = threadIdx.x;
#pragma unroll
    for (int q = 0; q < 8; ++q) {
        int s = tid + q * 256;
        int r = s >> 5, c4 = (s & 31) << 2;
        int gr = m0 + r; if (gr >= M) gr = M - 1;
        float4 f = *reinterpret_cast<const float4*>(X + (size_t)gr * DIM + c4);
        float v[4] = {f.x, f.y, f.z, f.w};
        uint32_t ph[2], pl[2];
#pragma unroll
        for (int e = 0; e < 2; ++e) {
            __half h0 = __float2half_rn(v[2 * e]), h1 = __float2half_rn(v[2 * e + 1]);
            __half l0 = __float2half_rn(v[2 * e] - __half2float(h0));
            __half l1 = __float2half_rn(v[2 * e + 1] - __half2float(h1));
            ph[e] = ((uint32_t)__half_as_ushort(h1) << 16) | __half_as_ushort(h0);
            pl[e] = ((uint32_t)__half_as_ushort(l1) << 16) | __half_as_ushort(l0);
        }
        *reinterpret_cast<uint2*>(sm + offh + r * 272 + (c4 << 1)) = make_uint2(ph[0], ph[1]);
        *reinterpret_cast<uint2*>(sm + offl + r * 272 + (c4 << 1)) = make_uint2(pl[0], pl[1]);
    }
}
// f32 -> single fp16 into one 64-row tile (tail kernel, 256 thr)
__device__ __forceinline__ void load_x_half64(char* sm, int off,
                                              const float* __restrict__ X, int m0, int M) {
    int tid = threadIdx.x;
#pragma unroll
    for (int q = 0; q < 8; ++q) {
        int s = tid + q * 256;
        int r = s >> 5, c4 = (s & 31) << 2;
        int gr = m0 + r; if (gr >= M) gr = M - 1;
        float4 f = *reinterpret_cast<const float4*>(X + (size_t)gr * DIM + c4);
        __half2 h01 = __floats2half2_rn(f.x, f.y);
        __half2 h23 = __floats2half2_rn(f.z, f.w);
        *reinterpret_cast<uint2*>(sm + off + r * 272 + (c4 << 1)) =
            make_uint2(*reinterpret_cast<uint32_t*>(&h01), *reinterpret_cast<uint32_t*>(&h23));
    }
}

// ---------------- B-fragment loader: ldmatrix.trans on [k][n] smem ----------------
__device__ __forceinline__ void ldB(uint32_t* w4, uint32_t base, int k0, int n0w, int jj, int lane) {
    int kk = k0 + ((lane >> 3) & 1) * 8 + (lane & 7);
    int nn = n0w + (jj + (lane >> 4)) * 8;
    ldmat_x4_trans(w4, base + (uint32_t)(kk * 272 + nn * 2));
}

// ---------------- 2-product core (head, 32x32 warp tile): d += Ah@W + Al@W ----------------
__device__ __forceinline__ void gemm_tiles2(uint32_t smb, int offAh, int offAl, int offW,
                                            int m0w, int n0w, int lane,
                                            float (&d)[2][4][4]) {
#pragma unroll
    for (int k0 = 0; k0 < 128; k0 += 16) {
        uint32_t ah[2][4], al[2][4];
#pragma unroll
        for (int i = 0; i < 2; ++i) {
            uint32_t ra = (uint32_t)((m0w + i * 16 + (lane & 15)) * 272 +
                                     ((k0 + ((lane >> 4) << 3)) << 1));
            ldmat_x4(ah[i], smb + offAh + ra);
            ldmat_x4(al[i], smb + offAl + ra);
        }
        uint2 wb[4];
#pragma unroll
        for (int jj = 0; jj < 4; jj += 2) {
            uint32_t w4[4];
            ldB(w4, smb + offW, k0, n0w, jj, lane);
            wb[jj]     = make_uint2(w4[0], w4[1]);
            wb[jj + 1] = make_uint2(w4[2], w4[3]);
        }
#pragma unroll
        for (int j = 0; j < 4; ++j) {
            hmma(d[0][j], ah[0], wb[j]);
            hmma(d[1][j], ah[1], wb[j]);
        }
#pragma unroll
        for (int j = 0; j < 4; ++j) {
            hmma(d[0][j], al[0], wb[j]);
            hmma(d[1][j], al[1], wb[j]);
        }
    }
}
// ---------------- 1-product core (tail, 32x32 warp tile): d += A@W ----------------
__device__ __forceinline__ void gemm_tiles1(uint32_t smb, int offA, int offW,
                                            int m0w, int n0w, int lane,
                                            float (&d)[2][4][4]) {
#pragma unroll
    for (int k0 = 0; k0 < 128; k0 += 16) {
        uint32_t a[2][4];
#pragma unroll
        for (int i = 0; i < 2; ++i) {
            uint32_t ra = (uint32_t)((m0w + i * 16 + (lane & 15)) * 272 +
                                     ((k0 + ((lane >> 4) << 3)) << 1));
            ldmat_x4(a[i], smb + offA + ra);
        }
        uint2 wb[4];
#pragma unroll
        for (int jj = 0; jj < 4; jj += 2) {
            uint32_t w4[4];
            ldB(w4, smb + offW, k0, n0w, jj, lane);
            wb[jj]     = make_uint2(w4[0], w4[1]);
            wb[jj + 1] = make_uint2(w4[2], w4[3]);
        }
#pragma unroll
        for (int j = 0; j < 4; ++j) {
            hmma(d[0][j], a[0], wb[j]);
            hmma(d[1][j], a[1], wb[j]);
        }
    }
}
__device__ __forceinline__ void zero_d(float (&d)[2][4][4]) {
#pragma unroll
    for (int i = 0; i < 2; ++i)
#pragma unroll
        for (int j = 0; j < 4; ++j)
#pragma unroll
            for (int e = 0; e < 4; ++e) d[i][j][e] = 0.f;
}
// write 32x32 register tile into smem as single fp16 (bias + optional relu)
template<bool RELU>
__device__ __forceinline__ void store_smem_half(char* sm, int off,
        float (&d)[2][4][4], const float* __restrict__ bias, float bscale,
        int m0w, int n0w, int lane) {
    int g = lane >> 2, tg = lane & 3;
#pragma unroll
    for (int j = 0; j < 4; ++j) {
        int c = n0w + j * 8 + 2 * tg;
        float b0 = bscale * __ldg(bias + c), b1 = bscale * __ldg(bias + c + 1);
#pragma unroll
        for (int i = 0; i < 2; ++i)
#pragma unroll
            for (int h = 0; h < 2; ++h) {
                int r = m0w + i * 16 + g + h * 8;
                float v0 = d[i][j][2 * h] + b0, v1 = d[i][j][2 * h + 1] + b1;
                if (RELU) { v0 = fmaxf(v0, 0.f); v1 = fmaxf(v1, 0.f); }
                __half2 hv = __floats2half2_rn(v0, v1);
                *reinterpret_cast<uint32_t*>(sm + off + r * 272 + c * 2) =
                    *reinterpret_cast<uint32_t*>(&hv);
            }
    }
}

// ---------------- head kernel: [A|B] = X @ [W1top|W1bot]; A += b1 (f32), B -> fp16 ----------------
// fp16 w1 via cp.async (pre-converted by conv_w1_kernel). smem = 2*TILE64 + 2*WTILE = 104448
__global__ __launch_bounds__(256, 2)
void head_kernel(const float* __restrict__ X,
                 const __half* __restrict__ w1, const float* __restrict__ msgb1,
                 float* __restrict__ outA, __half* __restrict__ outB, int M)
{
    constexpr int S0 = 0, S1 = TILE64, W0 = 2 * TILE64, W1 = 2 * TILE64 + WTILE;
    extern __shared__ char smem[];
    const uint32_t smb = smem_u32(smem);
    const int tid = threadIdx.x, wid = tid >> 5, lane = tid & 31;
    const int g = lane >> 2, tg = lane & 3;
    const int m0 = blockIdx.x * 64;
    const int m0w = (wid & 1) * 32, n0w = (wid >> 1) * 32;

    cp_w_tile(smb + W0, w1);                  // W1top: k-rows 0-127
    cp_w_tile(smb + W1, w1 + 128 * 128);      // W1bot: k-rows 128-255
    CP_COMMIT();
    load_x_split64(smem, S0, S1, X, m0, M);
    CP_WAIT(0);
    __syncthreads();

#pragma unroll
    for (int p = 0; p < 2; ++p) {
        float d[2][4][4];
        zero_d(d);
        gemm_tiles2(smb, S0, S1, p ? W1 : W0, m0w, n0w, lane, d);
#pragma unroll
        for (int j = 0; j < 4; ++j) {
            int c = n0w + j * 8 + 2 * tg;
            float b0 = 0.f, b1 = 0.f;
            if (p == 0) { b0 = __ldg(msgb1 + c); b1 = __ldg(msgb1 + c + 1); }
#pragma unroll
            for (int i = 0; i < 2; ++i)
#pragma unroll
                for (int h = 0; h < 2; ++h) {
                    int m = m0 + m0w + i * 16 + g + h * 8;
                    if (m >= M) continue;
                    float v0 = d[i][j][2 * h] + b0, v1 = d[i][j][2 * h + 1] + b1;
                    if (p == 0) {
                        *reinterpret_cast<float2*>(outA + (size_t)m * DIM + c) =
                            make_float2(v0, v1);
                    } else {
                        *reinterpret_cast<__half2*>(outB + (size_t)m * DIM + c) =
                            __floats2half2_rn(v0, v1);
                    }
                }
        }
    }
}

// ---------------- fused tail: agg -> u -> out, X preloaded, cp.async double-buffered W ----------------
// smem = 2*TILE64 + 2*WTILE = 104448 -> 2 CTAs/SM
__global__ __launch_bounds__(256, 2)
void fused_tail_kernel(const __half* __restrict__ H,
                       const float* __restrict__ X,
                       const __half* __restrict__ w2, const __half* __restrict__ u1,
                       const __half* __restrict__ u2,
                       const float* __restrict__ msgb2, const float* __restrict__ updb1,
                       const float* __restrict__ updb2,
                       float* __restrict__ out, int M)
{
    constexpr int S0 = 0, S1 = TILE64, W0 = 2 * TILE64, W1 = 2 * TILE64 + WTILE;
    extern __shared__ char smem[];
    const uint32_t smb = smem_u32(smem);
    const int tid = threadIdx.x, wid = tid >> 5, lane = tid & 31;
    const int g = lane >> 2, tg = lane & 3;
    const int m0 = blockIdx.x * 64;
    const int m0w = (wid & 1) * 32, n0w = (wid >> 1) * 32;

    // prologue: g0 = {H, w2}, g1 = {u1 agg-part}; X -> S1 overlapped
    cp_a_tile(smb + S0, H, m0, M);
    cp_w_tile(smb + W0, w2);
    CP_COMMIT();                          // g0
    cp_w_tile(smb + W1, u1 + 128 * 128);  // u1 k-rows 128-255 (agg part)
    CP_COMMIT();                          // g1
    load_x_half64(smem, S1, X, m0, M);    // X -> S1 (regular loads, overlaps cp.async)
    CP_WAIT(1);                           // g0 done
    __syncthreads();

    // ---- stage 1: agg = H @ w2 + 32*b2 ----
    float d[2][4][4];
    zero_d(d);
    gemm_tiles1(smb, S0, W0, m0w, n0w, lane, d);
    __syncthreads();                      // H/w2 reads done
    store_smem_half<false>(smem, S0, d, msgb2, (float)MNBR, m0w, n0w, lane);  // agg -> S0
    cp_w_tile(smb + W0, u1);              // u1 k-rows 0-127 (X part) into freed W0
    CP_COMMIT();                          // g2
    CP_WAIT(1);                           // g1 done
    __syncthreads();                      // agg + u1-agg visible

    // ---- stage 2a: d = agg @ u1[128:] ----
    zero_d(d);
    gemm_tiles1(smb, S0, W1, m0w, n0w, lane, d);
    __syncthreads();                      // W1/S0 reads done
    cp_w_tile(smb + W1, u2);              // u2 into freed W1
    CP_COMMIT();                          // g3
    CP_WAIT(1);                           // g2 done
    __syncthreads();
    // ---- stage 2b: d += X @ u1[:128] ----
    gemm_tiles1(smb, S1, W0, m0w, n0w, lane, d);
    store_smem_half<true>(smem, S0, d, updb1, 1.f, m0w, n0w, lane);  // u -> S0 (2a S0 reads synced)
    CP_WAIT(0);                           // g3 done
    __syncthreads();                      // u stores + u2 visible

    // ---- stage 3: out = relu(X + u @ u2 + b2) ----
    zero_d(d);
    gemm_tiles1(smb, S0, W1, m0w, n0w, lane, d);
#pragma unroll
    for (int j = 0; j < 4; ++j) {
        int c = n0w + j * 8 + 2 * tg;
        float b0 = __ldg(updb2 + c), b1 = __ldg(updb2 + c + 1);
#pragma unroll
        for (int i = 0; i < 2; ++i)
#pragma unroll
            for (int h = 0; h < 2; ++h) {
                int m = m0 + m0w + i * 16 + g + h * 8;
                if (m >= M) continue;
                float2 rx = *reinterpret_cast<const float2*>(X + (size_t)m * DIM + c);
                float v0 = fmaxf(d[i][j][2 * h] + b0 + rx.x, 0.f);
                float v1 = fmaxf(d[i][j][2 * h + 1] + b1 + rx.y, 0.f);
                *reinterpret_cast<float2*>(out + (size_t)m * DIM + c) = make_float2(v0, v1);
            }
    }
}

// ---------------- gather + edge ReLU + sum; extra blocks convert tail weights ----------------
__global__ __launch_bounds__(256)
void gather_sum_kernel(const float* __restrict__ A,
                       const __half* __restrict__ B,
                       const void* __restrict__ idx_raw,
                       __half* __restrict__ H,
                       const float* __restrict__ msgW2, const float* __restrict__ updW1,
                       const float* __restrict__ updW2,
                       __half* __restrict__ w2, __half* __restrict__ u1,
                       __half* __restrict__ u2, int M)
{
    if (blockIdx.x >= NGATHER) {
        // weight conversion blocks: 64 blocks x 1024 elems, elementwise f32->fp16
        int e = (blockIdx.x - NGATHER) * 1024 + threadIdx.x * 4;
        const float* src; __half* dst; int off;
        if (e < 16384)      { src = msgW2; dst = w2; off = e; }
        else if (e < 49152) { src = updW1; dst = u1; off = e - 16384; }
        else                { src = updW2; dst = u2; off = e - 49152; }
        float4 f = *reinterpret_cast<const float4*>(src + off);
        __half2 h01 = __floats2half2_rn(f.x, f.y);
        __half2 h23 = __floats2half2_rn(f.z, f.w);
        *reinterpret_cast<uint2*>(dst + off) =
            make_uint2(*reinterpret_cast<uint32_t*>(&h01), *reinterpret_cast<uint32_t*>(&h23));
        return;
    }

    int node = blockIdx.x * 8 + (threadIdx.x >> 5);
    int lane = threadIdx.x & 31;
    if (node >= M) return;

    // int32 vs int64 index detection (int64 little-endian -> odd words all zero)
    const int* idx32 = (const int*)idx_raw;
    int w = idx32[(size_t)node * 32 + lane];
    unsigned zmask = __ballot_sync(0xffffffffu, w == 0);
    int j;
    if ((zmask & 0xAAAAAAAAu) == 0xAAAAAAAAu)
        j = (int)((const long long*)idx_raw)[(size_t)node * 32 + lane];
    else
        j = w;

    float4 a = reinterpret_cast<const float4*>(A + (size_t)node * DIM)[lane];
    float4 acc = make_float4(0.f, 0.f, 0.f, 0.f);
#pragma unroll
    for (int m = 0; m < 32; ++m) {
        int jm = __shfl_sync(0xffffffffu, j, m);
        uint2 raw = __ldg(reinterpret_cast<const uint2*>(B + (size_t)jm * DIM) + lane);
        float2 f01 = __half22float2(*reinterpret_cast<__half2*>(&raw.x));
        float2 f23 = __half22float2(*reinterpret_cast<__half2*>(&raw.y));
        acc.x += fmaxf(a.x + f01.x, 0.f);
        acc.y += fmaxf(a.y + f01.y, 0.f);
        acc.z += fmaxf(a.z + f23.x, 0.f);
        acc.w += fmaxf(a.w + f23.y, 0.f);
    }
    __half2 h01 = __floats2half2_rn(acc.x, acc.y);
    __half2 h23 = __floats2half2_rn(acc.z, acc.w);
    reinterpret_cast<uint2*>(H + (size_t)node * DIM)[lane] =
        make_uint2(*reinterpret_cast<uint32_t*>(&h01), *reinterpret_cast<uint32_t*>(&h23));
}

// ---------------- launch ----------------
extern "C" void kernel_launch(void* const* d_in, const int* in_sizes, int n_in,
                              void* d_out, int out_size)
{
    const float* X     = (const float*)d_in[0];
    const void*  idx   = d_in[2];
    const float* msgW1 = (const float*)d_in[3];
    const float* msgb1 = (const float*)d_in[4];
    const float* msgW2 = (const float*)d_in[5];
    const float* msgb2 = (const float*)d_in[6];
    const float* updW1 = (const float*)d_in[7];
    const float* updb1 = (const float*)d_in[8];
    const float* updW2 = (const float*)d_in[9];
    const float* updb2 = (const float*)d_in[10];
    float* out = (float*)d_out;

    float* A; __half* B;
    __half *H, *w1, *w2, *u1, *u2;
    cudaGetSymbolAddress((void**)&A, g_A);   cudaGetSymbolAddress((void**)&B, g_B);
    cudaGetSymbolAddress((void**)&H, g_H);
    cudaGetSymbolAddress((void**)&w1, g_w1); cudaGetSymbolAddress((void**)&w2, g_w2);
    cudaGetSymbolAddress((void**)&u1, g_u1); cudaGetSymbolAddress((void**)&u2, g_u2);

    const int M = NATOMS;
    const int SMEM = 2 * TILE64 + 2 * WTILE;   // 104448 -> 2 CTAs/SM
    cudaFuncSetAttribute(head_kernel, cudaFuncAttributeMaxDynamicSharedMemorySize, SMEM);
    cudaFuncSetAttribute(fused_tail_kernel, cudaFuncAttributeMaxDynamicSharedMemorySize, SMEM);

    conv_w1_kernel<<<32, 256>>>(msgW1, w1);
    head_kernel<<<MGRID64, 256, SMEM>>>(X, w1, msgb1, A, B, M);
    gather_sum_kernel<<<NGATHER + 64, 256>>>(A, B, idx, H,
                                             msgW2, updW1, updW2, w2, u1, u2, M);
    fused_tail_kernel<<<MGRID64, 256, SMEM>>>(H, X, w2, u1, u2,
                                              msgb2, updb1, updb2, out, M);

    (void)in_sizes; (void)n_in; (void)out_size;
}

// round 15
// speedup vs baseline: 1.0327x; 1.0287x over previous
#include <cuda_runtime.h>
#include <cuda_fp16.h>
#include <cstdint>

#define NATOMS 25000
#define MNBR 32
#define DIM 128
#define MGRID64 391          // ceil(25000/64)
#define TILE64 17408         // 64 rows * 272B stride
#define WTILE 34816          // 128 rows * 272B stride

// ---------------- scratch (device globals) ----------------
__device__ float g_A[(size_t)NATOMS * DIM];           // X@W1top + b1 (f32, gather self term)
__device__ __half g_B[(size_t)NATOMS * DIM];          // X@W1bot (fp16, gather bulk reads)
__device__ __half g_H[(size_t)NATOMS * DIM];          // gather output (fp16)
// transposed single-fp16 weights: Wt[n][k] row-major
__device__ __half g_w1[256 * 128];   // [W1top^T | W1bot^T]
__device__ __half g_w2[128 * 128];   // msgW2^T
__device__ __half g_u1[128 * 256];   // updW1^T (N=128,K=256)
__device__ __half g_u2[128 * 128];   // updW2^T

// ---------------- helpers ----------------
__device__ __forceinline__ uint32_t smem_u32(const void* p) {
    uint32_t a;
    asm("{ .reg .u64 t; cvta.to.shared.u64 t, %1; cvt.u32.u64 %0, t; }" : "=r"(a) : "l"(p));
    return a;
}
__device__ __forceinline__ void ldmat_x4(uint32_t* r, uint32_t a) {
    asm volatile("ldmatrix.sync.aligned.m8n8.x4.shared.b16 {%0,%1,%2,%3}, [%4];"
        : "=r"(r[0]), "=r"(r[1]), "=r"(r[2]), "=r"(r[3]) : "r"(a));
}
__device__ __forceinline__ void hmma(float* d, const uint32_t* a, uint2 b) {
    asm volatile("mma.sync.aligned.m16n8k16.row.col.f32.f16.f16.f32 "
        "{%0,%1,%2,%3}, {%4,%5,%6,%7}, {%8,%9}, {%0,%1,%2,%3};"
        : "+f"(d[0]), "+f"(d[1]), "+f"(d[2]), "+f"(d[3])
        : "r"(a[0]), "r"(a[1]), "r"(a[2]), "r"(a[3]), "r"(b.x), "r"(b.y));
}
__device__ __forceinline__ void cp16(uint32_t dst, const void* src) {
    asm volatile("cp.async.cg.shared.global [%0], [%1], 16;" :: "r"(dst), "l"(src) : "memory");
}
#define CP_COMMIT() asm volatile("cp.async.commit_group;" ::: "memory")
#define CP_WAIT(n)  asm volatile("cp.async.wait_group %0;" :: "n"(n) : "memory")

// ---------------- weight transpose + fp16 cast: tiled, coalesced ----------------
// 24 blocks, each transposes one 64x64 tile through smem.
__global__ __launch_bounds__(256)
void conv_w_kernel(const float* __restrict__ msgW1,
                   const float* __restrict__ msgW2,
                   const float* __restrict__ updW1,
                   const float* __restrict__ updW2,
                   __half* __restrict__ w1, __half* __restrict__ w2,
                   __half* __restrict__ u1, __half* __restrict__ u2) {
    __shared__ float t[64][65];
    const int b = blockIdx.x, tid = threadIdx.x;

    const float* src; __half* dst;
    int srow0, scol0, drow0, dcol0, dstride;
    if (b < 8) {                       // w1: dst [256 n][128 k]
        int dn = b >> 1, dk = b & 1;
        src = (dn < 2) ? msgW1 : (msgW1 + 128 * 128);
        srow0 = dk * 64; scol0 = (dn & 1) * 64;
        if (dn >= 2) scol0 = (dn - 2) * 64; else scol0 = dn * 64;
        dst = w1; dstride = 128; drow0 = dn * 64; dcol0 = dk * 64;
    } else if (b < 12) {               // w2: dst [128 n][128 k]
        int i = b - 8; int dn = i >> 1, dk = i & 1;
        src = msgW2; srow0 = dk * 64; scol0 = dn * 64;
        dst = w2; dstride = 128; drow0 = dn * 64; dcol0 = dk * 64;
    } else if (b < 20) {               // u1: dst [128 n][256 k]  (src updW1 [256 k][128 n])
        int i = b - 12; int dn = i >> 2, dk = i & 3;
        src = updW1; srow0 = dk * 64; scol0 = dn * 64;
        dst = u1; dstride = 256; drow0 = dn * 64; dcol0 = dk * 64;
    } else {                           // u2: dst [128 n][128 k]
        int i = b - 20; int dn = i >> 1, dk = i & 1;
        src = updW2; srow0 = dk * 64; scol0 = dn * 64;
        dst = u2; dstride = 128; drow0 = dn * 64; dcol0 = dk * 64;
    }

    // coalesced f32 read of the 64x64 src tile
#pragma unroll
    for (int q = 0; q < 4; ++q) {
        int s = tid + q * 256;
        int r = s >> 4, c4 = (s & 15) << 2;
        float4 f = *reinterpret_cast<const float4*>(src + (size_t)(srow0 + r) * 128 + scol0 + c4);
        t[r][c4 + 0] = f.x; t[r][c4 + 1] = f.y; t[r][c4 + 2] = f.z; t[r][c4 + 3] = f.w;
    }
    __syncthreads();
    // coalesced fp16 write of the transposed tile: dst[drow0+r][dcol0+c] = t[c][r]
#pragma unroll
    for (int q = 0; q < 4; ++q) {
        int s = tid + q * 256;
        int r = s >> 4, c4 = (s & 15) << 2;
        __half2 h01 = __floats2half2_rn(t[c4 + 0][r], t[c4 + 1][r]);
        __half2 h23 = __floats2half2_rn(t[c4 + 2][r], t[c4 + 3][r]);
        *reinterpret_cast<uint2*>(dst + (size_t)(drow0 + r) * dstride + dcol0 + c4) =
            make_uint2(*reinterpret_cast<uint32_t*>(&h01), *reinterpret_cast<uint32_t*>(&h23));
    }
}

// ---------------- async tile copies (272B row stride), 256 threads ----------------
__device__ __forceinline__ void cp_w_tile(uint32_t smoff, const __half* __restrict__ src,
                                          int kstride, int k0) {
    int tid = threadIdx.x;
#pragma unroll
    for (int q = 0; q < 8; ++q) {
        int s = tid + q * 256;
        int r = s >> 4, c8 = (s & 15) << 3;
        cp16(smoff + r * 272 + (c8 << 1), src + (size_t)r * kstride + k0 + c8);
    }
}
// 64-row fp16 A tile via cp.async
__device__ __forceinline__ void cp_a_tile(uint32_t smoff, const __half* __restrict__ src,
                                          int m0, int M) {
    int tid = threadIdx.x;
#pragma unroll
    for (int q = 0; q < 4; ++q) {
        int s = tid + q * 256;
        int r = s >> 4, c8 = (s & 15) << 3;
        int gr = m0 + r; if (gr >= M) gr = M - 1;
        cp16(smoff + r * 272 + (c8 << 1), src + (size_t)gr * DIM + c8);
    }
}
// f32 -> fp16 hi/lo split into two 64-row tiles (head kernel, 256 thr)
__device__ __forceinline__ void load_x_split64(char* sm, int offh, int offl,
                                               const float* __restrict__ X, int m0, int M) {
    int tid = threadIdx.x;
#pragma unroll
    for (int q = 0; q < 8; ++q) {
        int s = tid + q * 256;
        int r = s >> 5, c4 = (s & 31) << 2;
        int gr = m0 + r; if (gr >= M) gr = M - 1;
        float4 f = *reinterpret_cast<const float4*>(X + (size_t)gr * DIM + c4);
        float v[4] = {f.x, f.y, f.z, f.w};
        uint32_t ph[2], pl[2];
#pragma unroll
        for (int e = 0; e < 2; ++e) {
            __half h0 = __float2half_rn(v[2 * e]), h1 = __float2half_rn(v[2 * e + 1]);
            __half l0 = __float2half_rn(v[2 * e] - __half2float(h0));
            __half l1 = __float2half_rn(v[2 * e + 1] - __half2float(h1));
            ph[e] = ((uint32_t)__half_as_ushort(h1) << 16) | __half_as_ushort(h0);
            pl[e] = ((uint32_t)__half_as_ushort(l1) << 16) | __half_as_ushort(l0);
        }
        *reinterpret_cast<uint2*>(sm + offh + r * 272 + (c4 << 1)) = make_uint2(ph[0], ph[1]);
        *reinterpret_cast<uint2*>(sm + offl + r * 272 + (c4 << 1)) = make_uint2(pl[0], pl[1]);
    }
}
// f32 -> single fp16 into one 64-row tile (tail kernel, 256 thr)
__device__ __forceinline__ void load_x_half64(char* sm, int off,
                                              const float* __restrict__ X, int m0, int M) {
    int tid = threadIdx.x;
#pragma unroll
    for (int q = 0; q < 8; ++q) {
        int s = tid + q * 256;
        int r = s >> 5, c4 = (s & 31) << 2;
        int gr = m0 + r; if (gr >= M) gr = M - 1;
        float4 f = *reinterpret_cast<const float4*>(X + (size_t)gr * DIM + c4);
        __half2 h01 = __floats2half2_rn(f.x, f.y);
        __half2 h23 = __floats2half2_rn(f.z, f.w);
        *reinterpret_cast<uint2*>(sm + off + r * 272 + (c4 << 1)) =
            make_uint2(*reinterpret_cast<uint32_t*>(&h01), *reinterpret_cast<uint32_t*>(&h23));
    }
}

// ---------------- 2-product core (head, 32x32 warp tile): d += Ah@W + Al@W ----------------
__device__ __forceinline__ void gemm_tiles2(uint32_t smb, int offAh, int offAl, int offW,
                                            int m0w, int n0w, int lane,
                                            float (&d)[2][4][4]) {
#pragma unroll
    for (int k0 = 0; k0 < 128; k0 += 16) {
        uint32_t ah[2][4], al[2][4];
#pragma unroll
        for (int i = 0; i < 2; ++i) {
            uint32_t ra = (uint32_t)((m0w + i * 16 + (lane & 15)) * 272 +
                                     ((k0 + ((lane >> 4) << 3)) << 1));
            ldmat_x4(ah[i], smb + offAh + ra);
            ldmat_x4(al[i], smb + offAl + ra);
        }
        uint2 wb[4];
#pragma unroll
        for (int jj = 0; jj < 4; jj += 2) {
            uint32_t rb = (uint32_t)((n0w + (jj + ((lane >> 4) & 1)) * 8 + (lane & 7)) * 272 +
                                     ((k0 + (((lane >> 3) & 1) << 3)) << 1));
            uint32_t w4[4];
            ldmat_x4(w4, smb + offW + rb);
            wb[jj]     = make_uint2(w4[0], w4[1]);
            wb[jj + 1] = make_uint2(w4[2], w4[3]);
        }
#pragma unroll
        for (int j = 0; j < 4; ++j) {
            hmma(d[0][j], ah[0], wb[j]);
            hmma(d[1][j], ah[1], wb[j]);
        }
#pragma unroll
        for (int j = 0; j < 4; ++j) {
            hmma(d[0][j], al[0], wb[j]);
            hmma(d[1][j], al[1], wb[j]);
        }
    }
}
// ---------------- 1-product core (tail, 32x32 warp tile): d += A@W ----------------
__device__ __forceinline__ void gemm_tiles1(uint32_t smb, int offA, int offW,
                                            int m0w, int n0w, int lane,
                                            float (&d)[2][4][4]) {
#pragma unroll
    for (int k0 = 0; k0 < 128; k0 += 16) {
        uint32_t a[2][4];
#pragma unroll
        for (int i = 0; i < 2; ++i) {
            uint32_t ra = (uint32_t)((m0w + i * 16 + (lane & 15)) * 272 +
                                     ((k0 + ((lane >> 4) << 3)) << 1));
            ldmat_x4(a[i], smb + offA + ra);
        }
        uint2 wb[4];
#pragma unroll
        for (int jj = 0; jj < 4; jj += 2) {
            uint32_t rb = (uint32_t)((n0w + (jj + ((lane >> 4) & 1)) * 8 + (lane & 7)) * 272 +
                                     ((k0 + (((lane >> 3) & 1) << 3)) << 1));
            uint32_t w4[4];
            ldmat_x4(w4, smb + offW + rb);
            wb[jj]     = make_uint2(w4[0], w4[1]);
            wb[jj + 1] = make_uint2(w4[2], w4[3]);
        }
#pragma unroll
        for (int j = 0; j < 4; ++j) {
            hmma(d[0][j], a[0], wb[j]);
            hmma(d[1][j], a[1], wb[j]);
        }
    }
}
__device__ __forceinline__ void zero_d(float (&d)[2][4][4]) {
#pragma unroll
    for (int i = 0; i < 2; ++i)
#pragma unroll
        for (int j = 0; j < 4; ++j)
#pragma unroll
            for (int e = 0; e < 4; ++e) d[i][j][e] = 0.f;
}
// write 32x32 register tile into smem as single fp16 (bias + optional relu)
template<bool RELU>
__device__ __forceinline__ void store_smem_half(char* sm, int off,
        float (&d)[2][4][4], const float* __restrict__ bias, float bscale,
        int m0w, int n0w, int lane) {
    int g = lane >> 2, tg = lane & 3;
#pragma unroll
    for (int j = 0; j < 4; ++j) {
        int c = n0w + j * 8 + 2 * tg;
        float b0 = bscale * __ldg(bias + c), b1 = bscale * __ldg(bias + c + 1);
#pragma unroll
        for (int i = 0; i < 2; ++i)
#pragma unroll
            for (int h = 0; h < 2; ++h) {
                int r = m0w + i * 16 + g + h * 8;
                float v0 = d[i][j][2 * h] + b0, v1 = d[i][j][2 * h + 1] + b1;
                if (RELU) { v0 = fmaxf(v0, 0.f); v1 = fmaxf(v1, 0.f); }
                __half2 hv = __floats2half2_rn(v0, v1);
                *reinterpret_cast<uint32_t*>(sm + off + r * 272 + c * 2) =
                    *reinterpret_cast<uint32_t*>(&hv);
            }
    }
}

// ---------------- head kernel: [A|B] = X @ [W1top|W1bot]; A += b1 (f32), B -> fp16 ----------------
// 256 thr (8 warps: 2m x 4n of 32x32), smem = 2*TILE64 + 2*WTILE = 104448 -> 2 CTAs/SM
__global__ __launch_bounds__(256, 2)
void head_kernel(const float* __restrict__ X,
                 const __half* __restrict__ w1, const float* __restrict__ msgb1,
                 float* __restrict__ outA, __half* __restrict__ outB, int M)
{
    constexpr int S0 = 0, S1 = TILE64, W0 = 2 * TILE64, W1 = 2 * TILE64 + WTILE;
    extern __shared__ char smem[];
    const uint32_t smb = smem_u32(smem);
    const int tid = threadIdx.x, wid = tid >> 5, lane = tid & 31;
    const int g = lane >> 2, tg = lane & 3;
    const int m0 = blockIdx.x * 64;
    const int m0w = (wid & 1) * 32, n0w = (wid >> 1) * 32;

    cp_w_tile(smb + W0, w1, 128, 0);
    cp_w_tile(smb + W1, w1 + 128 * 128, 128, 0);
    CP_COMMIT();
    load_x_split64(smem, S0, S1, X, m0, M);
    CP_WAIT(0);
    __syncthreads();

#pragma unroll
    for (int p = 0; p < 2; ++p) {
        float d[2][4][4];
        zero_d(d);
        gemm_tiles2(smb, S0, S1, p ? W1 : W0, m0w, n0w, lane, d);
#pragma unroll
        for (int j = 0; j < 4; ++j) {
            int c = n0w + j * 8 + 2 * tg;
            float b0 = 0.f, b1 = 0.f;
            if (p == 0) { b0 = __ldg(msgb1 + c); b1 = __ldg(msgb1 + c + 1); }
#pragma unroll
            for (int i = 0; i < 2; ++i)
#pragma unroll
                for (int h = 0; h < 2; ++h) {
                    int m = m0 + m0w + i * 16 + g + h * 8;
                    if (m >= M) continue;
                    float v0 = d[i][j][2 * h] + b0, v1 = d[i][j][2 * h + 1] + b1;
                    if (p == 0) {
                        *reinterpret_cast<float2*>(outA + (size_t)m * DIM + c) =
                            make_float2(v0, v1);
                    } else {
                        *reinterpret_cast<__half2*>(outB + (size_t)m * DIM + c) =
                            __floats2half2_rn(v0, v1);
                    }
                }
        }
    }
}

// ---------------- fused tail: agg -> u -> out, cp.async double-buffered weights ----------------
// 256 thr (8 warps: 2m x 4n of 32x32), smem = TILE64 + 2*WTILE = 87040 -> 2 CTAs/SM
__global__ __launch_bounds__(256, 2)
void fused_tail_kernel(const __half* __restrict__ H,
                       const float* __restrict__ X,
                       const __half* __restrict__ w2, const __half* __restrict__ u1,
                       const __half* __restrict__ u2,
                       const float* __restrict__ msgb2, const float* __restrict__ updb1,
                       const float* __restrict__ updb2,
                       float* __restrict__ out, int M)
{
    constexpr int S0 = 0, W0 = TILE64, W1 = TILE64 + WTILE;
    extern __shared__ char smem[];
    const uint32_t smb = smem_u32(smem);
    const int tid = threadIdx.x, wid = tid >> 5, lane = tid & 31;
    const int g = lane >> 2, tg = lane & 3;
    const int m0 = blockIdx.x * 64;
    const int m0w = (wid & 1) * 32, n0w = (wid >> 1) * 32;

    // prologue: g0 = {H, w2}, g1 = {u1 hi-k}
    cp_a_tile(smb + S0, H, m0, M);
    cp_w_tile(smb + W0, w2, 128, 0);
    CP_COMMIT();                         // g0
    cp_w_tile(smb + W1, u1, 256, 128);
    CP_COMMIT();                         // g1
    CP_WAIT(1);                          // g0 done (H + w2)
    __syncthreads();

    // ---- stage 1: agg = H @ w2 + 32*b2 ----
    float d[2][4][4];
    zero_d(d);
    gemm_tiles1(smb, S0, W0, m0w, n0w, lane, d);
    __syncthreads();                     // H/w2 reads done
    store_smem_half<false>(smem, S0, d, msgb2, (float)MNBR, m0w, n0w, lane);  // agg -> S0
    cp_w_tile(smb + W0, u1, 256, 0);     // prefetch u1 lo-k into freed W0
    CP_COMMIT();                         // g2
    CP_WAIT(1);                          // g1 done (u1 hi-k)
    __syncthreads();                     // agg stores visible

    // ---- stage 2a: d = agg @ u1[:,128:] ----
    zero_d(d);
    gemm_tiles1(smb, S0, W1, m0w, n0w, lane, d);
    __syncthreads();                     // agg/W1 reads done
    // ---- stage 2b: d += X @ u1[:,:128] (X overwrites agg buffer) ----
    load_x_half64(smem, S0, X, m0, M);
    cp_w_tile(smb + W1, u2, 128, 0);     // prefetch u2 into freed W1
    CP_COMMIT();                         // g3
    CP_WAIT(1);                          // g2 done (u1 lo-k)
    __syncthreads();
    gemm_tiles1(smb, S0, W0, m0w, n0w, lane, d);
    __syncthreads();                     // X/W0 reads done
    store_smem_half<true>(smem, S0, d, updb1, 1.f, m0w, n0w, lane);  // u -> S0
    CP_WAIT(0);                          // g3 done (u2)
    __syncthreads();

    // ---- stage 3: out = relu(X + u @ u2 + b2) ----
    zero_d(d);
    gemm_tiles1(smb, S0, W1, m0w, n0w, lane, d);
#pragma unroll
    for (int j = 0; j < 4; ++j) {
        int c = n0w + j * 8 + 2 * tg;
        float b0 = __ldg(updb2 + c), b1 = __ldg(updb2 + c + 1);
#pragma unroll
        for (int i = 0; i < 2; ++i)
#pragma unroll
            for (int h = 0; h < 2; ++h) {
                int m = m0 + m0w + i * 16 + g + h * 8;
                if (m >= M) continue;
                float2 rx = *reinterpret_cast<const float2*>(X + (size_t)m * DIM + c);
                float v0 = fmaxf(d[i][j][2 * h] + b0 + rx.x, 0.f);
                float v1 = fmaxf(d[i][j][2 * h + 1] + b1 + rx.y, 0.f);
                *reinterpret_cast<float2*>(out + (size_t)m * DIM + c) = make_float2(v0, v1);
            }
    }
}

// ---------------- gather + edge ReLU + sum (fp16 B reads, f32 math, fp16 out) ----------------
__global__ __launch_bounds__(256)
void gather_sum_kernel(const float* __restrict__ A,
                       const __half* __restrict__ B,
                       const void* __restrict__ idx_raw,
                       __half* __restrict__ H, int M)
{
    int node = blockIdx.x * 8 + (threadIdx.x >> 5);
    int lane = threadIdx.x & 31;
    if (node >= M) return;

    // int32 vs int64 index detection (int64 little-endian -> odd words all zero)
    const int* idx32 = (const int*)idx_raw;
    int w = idx32[(size_t)node * 32 + lane];
    unsigned zmask = __ballot_sync(0xffffffffu, w == 0);
    int j;
    if ((zmask & 0xAAAAAAAAu) == 0xAAAAAAAAu)
        j = (int)((const long long*)idx_raw)[(size_t)node * 32 + lane];
    else
        j = w;

    float4 a = reinterpret_cast<const float4*>(A + (size_t)node * DIM)[lane];
    float4 acc = make_float4(0.f, 0.f, 0.f, 0.f);
#pragma unroll
    for (int m = 0; m < 32; ++m) {
        int jm = __shfl_sync(0xffffffffu, j, m);
        uint2 raw = __ldg(reinterpret_cast<const uint2*>(B + (size_t)jm * DIM) + lane);
        float2 f01 = __half22float2(*reinterpret_cast<__half2*>(&raw.x));
        float2 f23 = __half22float2(*reinterpret_cast<__half2*>(&raw.y));
        acc.x += fmaxf(a.x + f01.x, 0.f);
        acc.y += fmaxf(a.y + f01.y, 0.f);
        acc.z += fmaxf(a.z + f23.x, 0.f);
        acc.w += fmaxf(a.w + f23.y, 0.f);
    }
    __half2 h01 = __floats2half2_rn(acc.x, acc.y);
    __half2 h23 = __floats2half2_rn(acc.z, acc.w);
    reinterpret_cast<uint2*>(H + (size_t)node * DIM)[lane] =
        make_uint2(*reinterpret_cast<uint32_t*>(&h01), *reinterpret_cast<uint32_t*>(&h23));
}

// ---------------- launch ----------------
extern "C" void kernel_launch(void* const* d_in, const int* in_sizes, int n_in,
                              void* d_out, int out_size)
{
    const float* X     = (const float*)d_in[0];
    const void*  idx   = d_in[2];
    const float* msgW1 = (const float*)d_in[3];
    const float* msgb1 = (const float*)d_in[4];
    const float* msgW2 = (const float*)d_in[5];
    const float* msgb2 = (const float*)d_in[6];
    const float* updW1 = (const float*)d_in[7];
    const float* updb1 = (const float*)d_in[8];
    const float* updW2 = (const float*)d_in[9];
    const float* updb2 = (const float*)d_in[10];
    float* out = (float*)d_out;

    float* A; __half* B;
    __half *H, *w1, *w2, *u1, *u2;
    cudaGetSymbolAddress((void**)&A, g_A);   cudaGetSymbolAddress((void**)&B, g_B);
    cudaGetSymbolAddress((void**)&H, g_H);
    cudaGetSymbolAddress((void**)&w1, g_w1); cudaGetSymbolAddress((void**)&w2, g_w2);
    cudaGetSymbolAddress((void**)&u1, g_u1); cudaGetSymbolAddress((void**)&u2, g_u2);

    const int M = NATOMS;
    const int SMEM_HEAD = 2 * TILE64 + 2 * WTILE;  // 104448 -> 2 CTAs/SM
    const int SMEM_TAIL = TILE64 + 2 * WTILE;      // 87040  -> 2 CTAs/SM
    cudaFuncSetAttribute(head_kernel, cudaFuncAttributeMaxDynamicSharedMemorySize, SMEM_HEAD);
    cudaFuncSetAttribute(fused_tail_kernel, cudaFuncAttributeMaxDynamicSharedMemorySize, SMEM_TAIL);

    conv_w_kernel<<<24, 256>>>(msgW1, msgW2, updW1, updW2, w1, w2, u1, u2);
    head_kernel<<<MGRID64, 256, SMEM_HEAD>>>(X, w1, msgb1, A, B, M);
    gather_sum_kernel<<<(M + 7) / 8, 256>>>(A, B, idx, H, M);
    fused_tail_kernel<<<MGRID64, 256, SMEM_TAIL>>>(H, X, w2, u1, u2,
                                                   msgb2, updb1, updb2, out, M);

    (void)in_sizes; (void)n_in; (void)out_size;
}